// round 9
// baseline (speedup 1.0000x reference)
#include <cuda_runtime.h>
#include <math.h>

// ---------------------------------------------------------------------------
// MTCNN P-net pyramid, B=4, 1080x1080x3, 12 scales.  R8:
//  - conv2: TX=8, output channels split across even/odd lanes (weight LDS /2)
//  - conv3head: TX=4, oc-split pairs + shfl-combined heads (weight LDS /2)
// Stages: resize_h | resize_v | conv1+pool | conv2 | conv3+heads
// ---------------------------------------------------------------------------

#define BATCH 4
#define HIN 1080
#define NS 12

typedef unsigned long long u64;

__device__ __forceinline__ u64 pack2(float x) {
    u64 r; asm("mov.b64 %0, {%1, %1};" : "=l"(r) : "f"(x)); return r;
}
__device__ __forceinline__ u64 pk2(float lo, float hi) {
    u64 r; asm("mov.b64 %0, {%1, %2};" : "=l"(r) : "f"(lo), "f"(hi)); return r;
}
__device__ __forceinline__ void unpk(u64 v, float& lo, float& hi) {
    asm("mov.b64 {%0, %1}, %2;" : "=f"(lo), "=f"(hi) : "l"(v));
}
__device__ __forceinline__ void ffma2(u64& d, u64 a, u64 b) {
    asm("fma.rn.f32x2 %0, %1, %2, %3;" : "=l"(d) : "l"(a), "l"(b), "l"(d));
}
__device__ __forceinline__ float lrelu(float z) { return z > 0.f ? z : 0.3f * z; }

__device__ float g_tmpH[28460160 + 1024];  // [4,1080,ws,3] interleaved
__device__ float g_img [10145112 + 1024];  // [4,3,hs,ws]  planar
__device__ float g_p1  [ 8377240 + 1024];  // [4,10,h2,w2] planar
__device__ float g_c2  [13127872 + 1024];  // [4,16,h3,w3] planar

struct Meta {
    int   hs[NS];
    float inv[NS], rinv[NS], scl[NS];
    int   offT[NS], offI[NS], offP[NS], offC[NS];
    int   noff[NS];
    int   ntot;
    int   bsRH[NS + 1], bsRV[NS + 1], bsCP[NS + 1], bsC2[NS + 1], bsC3[NS + 1];
};

__device__ __forceinline__ int fscale(const int* bs)
{
    int k = 0;
#pragma unroll
    for (int i = 1; i < NS; i++)
        if ((int)blockIdx.x >= bs[i]) k = i;
    return k;
}

// ---------------------------------------------------------------------------
// Stage 1: horizontal antialiased resize.
// ---------------------------------------------------------------------------
__global__ void k_resize_h(const float* __restrict__ in, Meta m)
{
    int k = fscale(m.bsRH);
    int ws = m.hs[k];
    float inv = m.inv[k], rinv = m.rinv[k];
    int idx = (blockIdx.x - m.bsRH[k]) * blockDim.x + threadIdx.x;
    if (idx >= BATCH * HIN * ws) return;
    int ox = idx % ws;
    int by = idx / ws;
    float sf = (ox + 0.5f) * inv - 0.5f;
    int j0 = (int)ceilf(sf - inv);  if (j0 < 0) j0 = 0;
    int j1 = (int)floorf(sf + inv); if (j1 > HIN - 1) j1 = HIN - 1;
    float a0 = 0.f, a1 = 0.f, a2 = 0.f, wsum = 0.f;
    const float* row = in + by * (HIN * 3) + j0 * 3;
    float fj = (float)j0;
    for (int j = j0; j <= j1; j++) {
        float wv = fmaxf(fmaf(fabsf(sf - fj), -rinv, 1.f), 0.f);
        wsum += wv;
        a0 = fmaf(wv, row[0], a0);
        a1 = fmaf(wv, row[1], a1);
        a2 = fmaf(wv, row[2], a2);
        row += 3; fj += 1.f;
    }
    float s = 1.f / wsum;
    float* o = g_tmpH + m.offT[k] + idx * 3;
    o[0] = a0 * s; o[1] = a1 * s; o[2] = a2 * s;
}

// ---------------------------------------------------------------------------
// Stage 2: vertical resize + (x-127.5)/128 -> planar img.
// ---------------------------------------------------------------------------
__global__ void k_resize_v(Meta m)
{
    int k = fscale(m.bsRV);
    int hs = m.hs[k], ws = hs;
    float inv = m.inv[k], rinv = m.rinv[k];
    int idx = (blockIdx.x - m.bsRV[k]) * blockDim.x + threadIdx.x;
    if (idx >= BATCH * hs * ws) return;
    int x  = idx % ws;
    int t  = idx / ws;
    int oy = t % hs;
    int b  = t / hs;
    float sf = (oy + 0.5f) * inv - 0.5f;
    int j0 = (int)ceilf(sf - inv);  if (j0 < 0) j0 = 0;
    int j1 = (int)floorf(sf + inv); if (j1 > HIN - 1) j1 = HIN - 1;
    float a0 = 0.f, a1 = 0.f, a2 = 0.f, wsum = 0.f;
    const float* p = g_tmpH + m.offT[k] + ((b * HIN + j0) * ws + x) * 3;
    int step = ws * 3;
    float fj = (float)j0;
    for (int j = j0; j <= j1; j++) {
        float wv = fmaxf(fmaf(fabsf(sf - fj), -rinv, 1.f), 0.f);
        wsum += wv;
        a0 = fmaf(wv, p[0], a0);
        a1 = fmaf(wv, p[1], a1);
        a2 = fmaf(wv, p[2], a2);
        p += step; fj += 1.f;
    }
    float s = 1.f / wsum;
    int plane = hs * ws, pix = oy * ws + x;
    float* o = g_img + m.offI[k] + b * 3 * plane + pix;
    o[0]         = (a0 * s - 127.5f) * (1.f / 128.f);
    o[plane]     = (a1 * s - 127.5f) * (1.f / 128.f);
    o[2 * plane] = (a2 * s - 127.5f) * (1.f / 128.f);
}

// ---------------------------------------------------------------------------
// Stage 3: conv3x3 3->10 + lrelu fused with 2x2/2 maxpool. Planar in/out.
// ---------------------------------------------------------------------------
__global__ void __launch_bounds__(128, 4)
k_conv1pool(const float* __restrict__ w, const float* __restrict__ bias, Meta m)
{
    __shared__ __align__(16) float ws_[27 * 12];
    __shared__ __align__(8)  float bs_[10];
    for (int i = threadIdx.x; i < 270; i += blockDim.x) {
        int e = i / 10, p = i - e * 10;
        ws_[e * 12 + p] = w[i];
    }
    if (threadIdx.x < 10) bs_[threadIdx.x] = bias[threadIdx.x];
    __syncthreads();

    int k = fscale(m.bsCP);
    int hs = m.hs[k], ws = hs;
    int h1 = hs - 2, w1 = ws - 2;
    int h2 = (h1 + 1) >> 1, w2 = (w1 + 1) >> 1;
    int idx = (blockIdx.x - m.bsCP[k]) * blockDim.x + threadIdx.x;
    if (idx >= BATCH * h2 * w2) return;
    int x = idx % w2;
    int t = idx / w2;
    int y = t % h2;
    int b = t / h2;
    int r0 = 2 * y, c0 = 2 * x;
    bool vr = (r0 + 1 < h1), vc = (c0 + 1 < w1);

    u64 acc[4][5];
    {
        const u64* bq = (const u64*)bs_;
#pragma unroll
        for (int p = 0; p < 4; p++) {
            u64 b0 = bq[0], b1 = bq[1], b2 = bq[2], b3 = bq[3], b4 = bq[4];
            acc[p][0] = b0; acc[p][1] = b1; acc[p][2] = b2; acc[p][3] = b3; acc[p][4] = b4;
        }
    }

    int plane = hs * ws;
    const float* imgb = g_img + m.offI[k] + b * 3 * plane;

#pragma unroll
    for (int ic = 0; ic < 3; ic++) {
        u64 pp[4][4];
#pragma unroll
        for (int i = 0; i < 4; i++) {
            int ry = r0 + i; if (ry > hs - 1) ry = hs - 1;
            const float* rp = imgb + ic * plane + ry * ws;
#pragma unroll
            for (int j = 0; j < 4; j++) {
                int cx = c0 + j; if (cx > ws - 1) cx = ws - 1;
                pp[i][j] = pack2(__ldg(rp + cx));
            }
        }
#pragma unroll
        for (int ky = 0; ky < 3; ky++)
#pragma unroll
        for (int kx = 0; kx < 3; kx++) {
            const float* wbase = ws_ + ((ky * 3 + kx) * 3 + ic) * 12;
            ulonglong2 w01 = *(const ulonglong2*)wbase;
            ulonglong2 w23 = *(const ulonglong2*)(wbase + 4);
            u64        w4  = *(const u64*)(wbase + 8);
            u64 wv[5] = { w01.x, w01.y, w23.x, w23.y, w4 };
#pragma unroll
            for (int q = 0; q < 5; q++) {
                ffma2(acc[0][q], pp[ky][kx],         wv[q]);
                ffma2(acc[1][q], pp[ky][kx + 1],     wv[q]);
                ffma2(acc[2][q], pp[ky + 1][kx],     wv[q]);
                ffma2(acc[3][q], pp[ky + 1][kx + 1], wv[q]);
            }
        }
    }

    int oplane = h2 * w2;
    float* ob = g_p1 + m.offP[k] + b * 10 * oplane + y * w2 + x;
#pragma unroll
    for (int q = 0; q < 5; q++) {
        float z0, z1, a0, a1, u0, u1;
        unpk(acc[0][q], z0, z1); a0 = lrelu(z0); a1 = lrelu(z1);
        if (vc) { unpk(acc[1][q], z0, z1); a0 = fmaxf(a0, lrelu(z0)); a1 = fmaxf(a1, lrelu(z1)); }
        if (vr) { unpk(acc[2][q], z0, z1); a0 = fmaxf(a0, lrelu(z0)); a1 = fmaxf(a1, lrelu(z1));
            if (vc) { unpk(acc[3][q], u0, u1); a0 = fmaxf(a0, lrelu(u0)); a1 = fmaxf(a1, lrelu(u1)); } }
        ob[(2 * q)     * oplane] = a0;
        ob[(2 * q + 1) * oplane] = a1;
    }
}

// ---------------------------------------------------------------------------
// Stage 4: conv3x3 10->16 + lrelu. TX=8 pixels/thread, 8 of 16 oc per thread
// (even lanes oc 0-7, odd lanes oc 8-15) -> halved weight-LDS per pixel.
// ---------------------------------------------------------------------------
__global__ void __launch_bounds__(128, 4)
k_conv2(const float* __restrict__ w, const float* __restrict__ bias, Meta m)
{
    __shared__ __align__(16) float ws_[1440];
    __shared__ __align__(8)  float bs_[16];
    {
        const float4* s4 = (const float4*)w;
        float4* d4 = (float4*)ws_;
        for (int i = threadIdx.x; i < 360; i += blockDim.x) d4[i] = s4[i];
        if (threadIdx.x < 16) bs_[threadIdx.x] = bias[threadIdx.x];
    }
    __syncthreads();

    int k = fscale(m.bsC2);
    int hs = m.hs[k];
    int hin = (hs - 1) >> 1, win = hin;
    int hout = hin - 2, wout = win - 2;
    int WG = (wout + 7) >> 3;
    int idx = (blockIdx.x - m.bsC2[k]) * blockDim.x + threadIdx.x;
    int half = idx & 1;
    int gid = idx >> 1;
    if (gid >= BATCH * hout * WG) return;
    int xg = gid % WG;
    int t2 = gid / WG;
    int y  = t2 % hout;
    int b  = t2 / hout;
    int x0 = xg * 8;

    u64 acc[8][4];
    {
        const u64* bq = (const u64*)bs_;
        u64 b0 = bq[half * 4 + 0], b1 = bq[half * 4 + 1];
        u64 b2 = bq[half * 4 + 2], b3 = bq[half * 4 + 3];
#pragma unroll
        for (int t = 0; t < 8; t++) {
            acc[t][0] = b0; acc[t][1] = b1; acc[t][2] = b2; acc[t][3] = b3;
        }
    }

    int plane = hin * win;
    const float* pb = g_p1 + m.offP[k] + b * 10 * plane;
    int xc[10];
#pragma unroll
    for (int t = 0; t < 10; t++) { int xx = x0 + t; xc[t] = xx > win - 1 ? win - 1 : xx; }

#pragma unroll
    for (int ky = 0; ky < 3; ky++) {
        const float* rbase = pb + (y + ky) * win;
#pragma unroll 2
        for (int ic = 0; ic < 10; ic++) {
            const float* rp = rbase + ic * plane;
            u64 vv[10];
#pragma unroll
            for (int t = 0; t < 10; t++) vv[t] = pack2(__ldg(rp + xc[t]));
#pragma unroll
            for (int kx = 0; kx < 3; kx++) {
                const ulonglong2* wq =
                    (const ulonglong2*)(ws_ + ((ky * 3 + kx) * 10 + ic) * 16 + half * 8);
                ulonglong2 wA = wq[0], wB = wq[1];
#pragma unroll
                for (int t = 0; t < 8; t++) {
                    ffma2(acc[t][0], vv[t + kx], wA.x);
                    ffma2(acc[t][1], vv[t + kx], wA.y);
                    ffma2(acc[t][2], vv[t + kx], wB.x);
                    ffma2(acc[t][3], vv[t + kx], wB.y);
                }
            }
        }
    }

    int oplane = hout * wout;
    float* ob = g_c2 + m.offC[k] + (b * 16 + half * 8) * oplane + y * wout;
#pragma unroll
    for (int t = 0; t < 8; t++) {
        int x = x0 + t;
        if (x < wout) {
#pragma unroll
            for (int q = 0; q < 4; q++) {
                float z0, z1;
                unpk(acc[t][q], z0, z1);
                ob[(2 * q)     * oplane + x] = lrelu(z0);
                ob[(2 * q + 1) * oplane + x] = lrelu(z1);
            }
        }
    }
}

// ---------------------------------------------------------------------------
// Stage 5: conv3x3 16->32 + lrelu + heads + boxes + mask.  TX=4 pixels/thread,
// 16 of 32 oc per thread (lane pairs); head partials combined via shfl_xor.
// Output layout: boxes[4][N][5] | reg[4][N][4] | mask[4][N]
// ---------------------------------------------------------------------------
__global__ void __launch_bounds__(128, 4)
k_conv3head(const float* __restrict__ w, const float* __restrict__ bias,
            const float* __restrict__ wp, const float* __restrict__ bp,
            const float* __restrict__ wr, const float* __restrict__ br,
            float* __restrict__ out, Meta m)
{
    __shared__ __align__(16) float ws_[4608];
    __shared__ __align__(8)  float cb_[32], hwp[64], hwr[128], hb[6];
    {
        const float4* s4 = (const float4*)w;
        float4* d4 = (float4*)ws_;
        for (int i = threadIdx.x; i < 1152; i += blockDim.x) d4[i] = s4[i];
        if (threadIdx.x < 32) cb_[threadIdx.x] = bias[threadIdx.x];
        if (threadIdx.x < 64) hwp[threadIdx.x] = wp[threadIdx.x];
        hwr[threadIdx.x] = wr[threadIdx.x];
        if (threadIdx.x == 64) { hb[0] = bp[0]; hb[1] = bp[1]; }
        if (threadIdx.x == 65) { hb[2] = br[0]; hb[3] = br[1]; hb[4] = br[2]; hb[5] = br[3]; }
    }
    __syncthreads();

    int k = fscale(m.bsC3);
    int hs = m.hs[k];
    int hin = ((hs - 1) >> 1) - 2, win = hin;
    int hout = hin - 2, wout = win - 2;
    int WG = (wout + 3) >> 2;
    int ngroups = BATCH * hout * WG;
    int idx = (blockIdx.x - m.bsC3[k]) * blockDim.x + threadIdx.x;
    int half = idx & 1;
    int gid = idx >> 1;
    bool alive = gid < ngroups;
    if (!alive) gid = ngroups - 1;          // keep lanes running for shfl
    int xg = gid % WG;
    int t2 = gid / WG;
    int y  = t2 % hout;
    int b  = t2 / hout;
    int x0 = xg * 4;

    u64 acc[4][8];
    {
        const u64* bq = (const u64*)cb_;     // 16 u64 (32 floats)
#pragma unroll
        for (int q = 0; q < 8; q++) {
            u64 bv = bq[half * 8 + q];
            acc[0][q] = bv; acc[1][q] = bv; acc[2][q] = bv; acc[3][q] = bv;
        }
    }

    int plane = hin * win;
    const float* cbase = g_c2 + m.offC[k] + b * 16 * plane;
    int xc[6];
#pragma unroll
    for (int t = 0; t < 6; t++) { int xx = x0 + t; xc[t] = xx > win - 1 ? win - 1 : xx; }

#pragma unroll
    for (int ky = 0; ky < 3; ky++) {
        const float* rbase = cbase + (y + ky) * win;
#pragma unroll 2
        for (int ic = 0; ic < 16; ic++) {
            const float* rp = rbase + ic * plane;
            u64 vv[6];
#pragma unroll
            for (int t = 0; t < 6; t++) vv[t] = pack2(__ldg(rp + xc[t]));
#pragma unroll
            for (int kx = 0; kx < 3; kx++) {
                const ulonglong2* wq =
                    (const ulonglong2*)(ws_ + ((ky * 3 + kx) * 16 + ic) * 32 + half * 16);
                ulonglong2 wA = wq[0], wB = wq[1], wC = wq[2], wD = wq[3];
#pragma unroll
                for (int t = 0; t < 4; t++) {
                    u64 v = vv[t + kx];
                    ffma2(acc[t][0], v, wA.x);
                    ffma2(acc[t][1], v, wA.y);
                    ffma2(acc[t][2], v, wB.x);
                    ffma2(acc[t][3], v, wB.y);
                    ffma2(acc[t][4], v, wC.x);
                    ffma2(acc[t][5], v, wC.y);
                    ffma2(acc[t][6], v, wD.x);
                    ffma2(acc[t][7], v, wD.y);
                }
            }
        }
    }

    int ntot = m.ntot;
    float scale = m.scl[k];
    int nbase = m.noff[k] + y * wout;
    float fy = (float)y;
    const u64* wp64 = (const u64*)hwp;
    const u64* wr64 = (const u64*)hwr;
    u64 zero = pk2(0.f, 0.f);

#pragma unroll
    for (int t = 0; t < 4; t++) {
        u64 zz = (half == 0) ? pk2(hb[0], hb[1]) : zero;
        u64 rA = (half == 0) ? pk2(hb[2], hb[3]) : zero;
        u64 rB = (half == 0) ? pk2(hb[4], hb[5]) : zero;
#pragma unroll
        for (int q = 0; q < 8; q++) {
            float z0, z1;
            unpk(acc[t][q], z0, z1);
            u64 v0 = pack2(lrelu(z0));
            u64 v1 = pack2(lrelu(z1));
            int c0 = half * 16 + 2 * q, c1 = c0 + 1;
            ffma2(zz, v0, wp64[c0]);         ffma2(zz, v1, wp64[c1]);
            ffma2(rA, v0, wr64[2 * c0]);     ffma2(rA, v1, wr64[2 * c1]);
            ffma2(rB, v0, wr64[2 * c0 + 1]); ffma2(rB, v1, wr64[2 * c1 + 1]);
        }
        // combine oc halves across the lane pair
        u64 zo = __shfl_xor_sync(0xffffffffu, zz, 1);
        u64 ao = __shfl_xor_sync(0xffffffffu, rA, 1);
        u64 bo = __shfl_xor_sync(0xffffffffu, rB, 1);

        int x = x0 + t;
        if (alive && half == 0 && x < wout) {
            float z0, z1, o0, o1, r0, r1, r2, r3;
            unpk(zz, z0, z1); unpk(zo, o0, o1); z0 += o0; z1 += o1;
            unpk(rA, r0, r1); unpk(ao, o0, o1); r0 += o0; r1 += o1;
            unpk(rB, r2, r3); unpk(bo, o0, o1); r2 += o0; r3 += o1;

            float score = 1.f / (1.f + expf(z0 - z1));
            int n = nbase + x;
            float fx = (float)x;
            float ulr = rintf((fy * 2.f + 1.f)  / scale);
            float ulc = rintf((fx * 2.f + 1.f)  / scale);
            float drr = rintf((fy * 2.f + 12.f) / scale);
            float drc = rintf((fx * 2.f + 12.f) / scale);

            float* pbx = out + (b * ntot + n) * 5;
            pbx[0] = ulr; pbx[1] = ulc; pbx[2] = drr; pbx[3] = drc; pbx[4] = score;

            float* prg = out + BATCH * ntot * 5 + (b * ntot + n) * 4;
            prg[0] = r0; prg[1] = r1; prg[2] = r2; prg[3] = r3;

            out[BATCH * ntot * 9 + b * ntot + n] = (score >= 0.6f) ? 1.f : 0.f;
        }
    }
}

// ---------------------------------------------------------------------------
extern "C" void kernel_launch(void* const* d_in, const int* in_sizes, int n_in,
                              void* d_out, int out_size)
{
    const float* inp = (const float*)d_in[0];
    const float* w1  = (const float*)d_in[1];
    const float* b1  = (const float*)d_in[2];
    const float* w2  = (const float*)d_in[3];
    const float* b2  = (const float*)d_in[4];
    const float* w3  = (const float*)d_in[5];
    const float* b3  = (const float*)d_in[6];
    const float* wp  = (const float*)d_in[7];
    const float* bp  = (const float*)d_in[8];
    const float* wr  = (const float*)d_in[9];
    const float* br  = (const float*)d_in[10];
    float* out = (float*)d_out;
    (void)in_sizes; (void)n_in; (void)out_size;

    Meta m;
    int ns = 0;
    {
        double s = 12.0 / 20.0, mm = s * 1080.0;
        while (mm >= 12.0 && ns < NS) {
            m.hs[ns]   = (int)ceil(1080.0 * s);
            m.inv[ns]  = (float)(1080.0 / (double)m.hs[ns]);
            m.rinv[ns] = (float)((double)m.hs[ns] / 1080.0);
            m.scl[ns]  = (float)s;
            ns++;
            s *= 0.709; mm *= 0.709;
        }
    }

    int oT = 0, oI = 0, oP = 0, oC = 0, ntot = 0;
    m.bsRH[0] = m.bsRV[0] = m.bsCP[0] = m.bsC2[0] = m.bsC3[0] = 0;
    for (int k = 0; k < ns; k++) {
        int hs = m.hs[k], ws = hs;
        int h1 = hs - 2;
        int h2 = (h1 + 1) / 2, w2d = h2;
        int h3 = h2 - 2, w3d = h3;
        int h4 = h3 - 2, w4 = h4;

        m.offT[k] = oT;  oT += BATCH * HIN * ws * 3;
        m.offI[k] = oI;  oI += BATCH * hs * ws * 3;
        m.offP[k] = oP;  oP += BATCH * h2 * w2d * 10;
        m.offC[k] = oC;  oC += BATCH * h3 * w3d * 16;
        m.noff[k] = ntot; ntot += h4 * w4;

        int T;
        T = BATCH * HIN * ws;                     m.bsRH[k+1] = m.bsRH[k] + (T + 255) / 256;
        T = BATCH * hs * ws;                      m.bsRV[k+1] = m.bsRV[k] + (T + 255) / 256;
        T = BATCH * h2 * w2d;                     m.bsCP[k+1] = m.bsCP[k] + (T + 127) / 128;
        T = 2 * BATCH * h3 * ((w3d + 7) / 8);     m.bsC2[k+1] = m.bsC2[k] + (T + 127) / 128;
        T = 2 * BATCH * h4 * ((w4 + 3) / 4);      m.bsC3[k+1] = m.bsC3[k] + (T + 127) / 128;
    }
    m.ntot = ntot;
    for (int k = ns; k < NS; k++) {
        m.hs[k] = m.hs[ns-1]; m.inv[k] = m.inv[ns-1];
        m.rinv[k] = m.rinv[ns-1]; m.scl[k] = m.scl[ns-1];
        m.offT[k] = m.offI[k] = m.offP[k] = m.offC[k] = 0; m.noff[k] = 0;
        m.bsRH[k+1] = m.bsRH[k]; m.bsRV[k+1] = m.bsRV[k];
        m.bsCP[k+1] = m.bsCP[k]; m.bsC2[k+1] = m.bsC2[k]; m.bsC3[k+1] = m.bsC3[k];
        m.bsRH[k] = 0x7fffffff; m.bsRV[k] = 0x7fffffff; m.bsCP[k] = 0x7fffffff;
        m.bsC2[k] = 0x7fffffff; m.bsC3[k] = 0x7fffffff;
    }

    k_resize_h <<<m.bsRH[ns], 256>>>(inp, m);
    k_resize_v <<<m.bsRV[ns], 256>>>(m);
    k_conv1pool<<<m.bsCP[ns], 128>>>(w1, b1, m);
    k_conv2    <<<m.bsC2[ns], 128>>>(w2, b2, m);
    k_conv3head<<<m.bsC3[ns], 128>>>(w3, b3, wp, bp, wr, br, out, m);
}

// round 10
// speedup vs baseline: 1.4161x; 1.4161x over previous
#include <cuda_runtime.h>
#include <math.h>

// ---------------------------------------------------------------------------
// MTCNN P-net pyramid, B=4, 1080x1080x3, 12 scales.  R9:
//  - conv2/conv3head: reverted to R7 shapes (TX=4 / TX=2, full OC per thread)
//  - resize_h: fused across ALL scales; one block per input row, row staged
//    in SMEM once, taps read from SMEM (12x less global input traffic)
// Stages: resize_h(all scales) | resize_v | conv1+pool | conv2 | conv3+heads
// ---------------------------------------------------------------------------

#define BATCH 4
#define HIN 1080
#define NS 12

typedef unsigned long long u64;

__device__ __forceinline__ u64 pack2(float x) {
    u64 r; asm("mov.b64 %0, {%1, %1};" : "=l"(r) : "f"(x)); return r;
}
__device__ __forceinline__ u64 pk2(float lo, float hi) {
    u64 r; asm("mov.b64 %0, {%1, %2};" : "=l"(r) : "f"(lo), "f"(hi)); return r;
}
__device__ __forceinline__ void unpk(u64 v, float& lo, float& hi) {
    asm("mov.b64 {%0, %1}, %2;" : "=f"(lo), "=f"(hi) : "l"(v));
}
__device__ __forceinline__ void ffma2(u64& d, u64 a, u64 b) {
    asm("fma.rn.f32x2 %0, %1, %2, %3;" : "=l"(d) : "l"(a), "l"(b), "l"(d));
}
__device__ __forceinline__ float lrelu(float z) { return z > 0.f ? z : 0.3f * z; }

__device__ float g_tmpH[28460160 + 1024];  // [4,1080,ws,3] interleaved
__device__ float g_img [10145112 + 1024];  // [4,3,hs,ws]  planar
__device__ float g_p1  [ 8377240 + 1024];  // [4,10,h2,w2] planar
__device__ float g_c2  [13127872 + 1024];  // [4,16,h3,w3] planar

struct Meta {
    int   hs[NS];
    float inv[NS], rinv[NS], scl[NS];
    int   offT[NS], offI[NS], offP[NS], offC[NS];
    int   offW[NS];          // cumulative ws (for fused resize_h item->scale)
    int   wsum;              // sum of ws over scales
    int   noff[NS];
    int   ntot;
    int   bsRV[NS + 1], bsCP[NS + 1], bsC2[NS + 1], bsC3[NS + 1];
};

__device__ __forceinline__ int fscale(const int* bs)
{
    int k = 0;
#pragma unroll
    for (int i = 1; i < NS; i++)
        if ((int)blockIdx.x >= bs[i]) k = i;
    return k;
}

// ---------------------------------------------------------------------------
// Stage 1: horizontal antialiased resize, ALL scales fused.
// One block per input row (b,y). Row staged in SMEM; every scale's outputs
// for this row are computed from the staged row.
// ---------------------------------------------------------------------------
__global__ void __launch_bounds__(256)
k_resize_h(const float* __restrict__ in, Meta m)
{
    __shared__ float srow[HIN * 3];
    int by = blockIdx.x;                       // b*1080 + y
    const float* rp = in + by * (HIN * 3);
    for (int i = threadIdx.x; i < HIN * 3; i += 256) srow[i] = rp[i];
    __syncthreads();

    for (int it = threadIdx.x; it < m.wsum; it += 256) {
        int k = 0;
#pragma unroll
        for (int i = 1; i < NS; i++)
            if (it >= m.offW[i]) k = i;
        int ox = it - m.offW[k];
        int ws = m.hs[k];
        float inv = m.inv[k], rinv = m.rinv[k];

        float sf = (ox + 0.5f) * inv - 0.5f;
        int j0 = (int)ceilf(sf - inv);  if (j0 < 0) j0 = 0;
        int j1 = (int)floorf(sf + inv); if (j1 > HIN - 1) j1 = HIN - 1;
        float a0 = 0.f, a1 = 0.f, a2 = 0.f, wsum = 0.f;
        const float* s = srow + j0 * 3;
        float fj = (float)j0;
        for (int j = j0; j <= j1; j++) {
            float wv = fmaxf(fmaf(fabsf(sf - fj), -rinv, 1.f), 0.f);
            wsum += wv;
            a0 = fmaf(wv, s[0], a0);
            a1 = fmaf(wv, s[1], a1);
            a2 = fmaf(wv, s[2], a2);
            s += 3; fj += 1.f;
        }
        float sc = 1.f / wsum;
        float* o = g_tmpH + m.offT[k] + (by * ws + ox) * 3;
        o[0] = a0 * sc; o[1] = a1 * sc; o[2] = a2 * sc;
    }
}

// ---------------------------------------------------------------------------
// Stage 2: vertical resize + (x-127.5)/128 -> planar img.
// ---------------------------------------------------------------------------
__global__ void k_resize_v(Meta m)
{
    int k = fscale(m.bsRV);
    int hs = m.hs[k], ws = hs;
    float inv = m.inv[k], rinv = m.rinv[k];
    int idx = (blockIdx.x - m.bsRV[k]) * blockDim.x + threadIdx.x;
    if (idx >= BATCH * hs * ws) return;
    int x  = idx % ws;
    int t  = idx / ws;
    int oy = t % hs;
    int b  = t / hs;
    float sf = (oy + 0.5f) * inv - 0.5f;
    int j0 = (int)ceilf(sf - inv);  if (j0 < 0) j0 = 0;
    int j1 = (int)floorf(sf + inv); if (j1 > HIN - 1) j1 = HIN - 1;
    float a0 = 0.f, a1 = 0.f, a2 = 0.f, wsum = 0.f;
    const float* p = g_tmpH + m.offT[k] + ((b * HIN + j0) * ws + x) * 3;
    int step = ws * 3;
    float fj = (float)j0;
    for (int j = j0; j <= j1; j++) {
        float wv = fmaxf(fmaf(fabsf(sf - fj), -rinv, 1.f), 0.f);
        wsum += wv;
        a0 = fmaf(wv, p[0], a0);
        a1 = fmaf(wv, p[1], a1);
        a2 = fmaf(wv, p[2], a2);
        p += step; fj += 1.f;
    }
    float s = 1.f / wsum;
    int plane = hs * ws, pix = oy * ws + x;
    float* o = g_img + m.offI[k] + b * 3 * plane + pix;
    o[0]         = (a0 * s - 127.5f) * (1.f / 128.f);
    o[plane]     = (a1 * s - 127.5f) * (1.f / 128.f);
    o[2 * plane] = (a2 * s - 127.5f) * (1.f / 128.f);
}

// ---------------------------------------------------------------------------
// Stage 3: conv3x3 3->10 + lrelu fused with 2x2/2 maxpool. Planar in/out.
// ---------------------------------------------------------------------------
__global__ void __launch_bounds__(128, 4)
k_conv1pool(const float* __restrict__ w, const float* __restrict__ bias, Meta m)
{
    __shared__ __align__(16) float ws_[27 * 12];
    __shared__ __align__(8)  float bs_[10];
    for (int i = threadIdx.x; i < 270; i += blockDim.x) {
        int e = i / 10, p = i - e * 10;
        ws_[e * 12 + p] = w[i];
    }
    if (threadIdx.x < 10) bs_[threadIdx.x] = bias[threadIdx.x];
    __syncthreads();

    int k = fscale(m.bsCP);
    int hs = m.hs[k], ws = hs;
    int h1 = hs - 2, w1 = ws - 2;
    int h2 = (h1 + 1) >> 1, w2 = (w1 + 1) >> 1;
    int idx = (blockIdx.x - m.bsCP[k]) * blockDim.x + threadIdx.x;
    if (idx >= BATCH * h2 * w2) return;
    int x = idx % w2;
    int t = idx / w2;
    int y = t % h2;
    int b = t / h2;
    int r0 = 2 * y, c0 = 2 * x;
    bool vr = (r0 + 1 < h1), vc = (c0 + 1 < w1);

    u64 acc[4][5];
    {
        const u64* bq = (const u64*)bs_;
#pragma unroll
        for (int p = 0; p < 4; p++) {
            u64 b0 = bq[0], b1 = bq[1], b2 = bq[2], b3 = bq[3], b4 = bq[4];
            acc[p][0] = b0; acc[p][1] = b1; acc[p][2] = b2; acc[p][3] = b3; acc[p][4] = b4;
        }
    }

    int plane = hs * ws;
    const float* imgb = g_img + m.offI[k] + b * 3 * plane;

#pragma unroll
    for (int ic = 0; ic < 3; ic++) {
        u64 pp[4][4];
#pragma unroll
        for (int i = 0; i < 4; i++) {
            int ry = r0 + i; if (ry > hs - 1) ry = hs - 1;
            const float* rp = imgb + ic * plane + ry * ws;
#pragma unroll
            for (int j = 0; j < 4; j++) {
                int cx = c0 + j; if (cx > ws - 1) cx = ws - 1;
                pp[i][j] = pack2(__ldg(rp + cx));
            }
        }
#pragma unroll
        for (int ky = 0; ky < 3; ky++)
#pragma unroll
        for (int kx = 0; kx < 3; kx++) {
            const float* wbase = ws_ + ((ky * 3 + kx) * 3 + ic) * 12;
            ulonglong2 w01 = *(const ulonglong2*)wbase;
            ulonglong2 w23 = *(const ulonglong2*)(wbase + 4);
            u64        w4  = *(const u64*)(wbase + 8);
            u64 wv[5] = { w01.x, w01.y, w23.x, w23.y, w4 };
#pragma unroll
            for (int q = 0; q < 5; q++) {
                ffma2(acc[0][q], pp[ky][kx],         wv[q]);
                ffma2(acc[1][q], pp[ky][kx + 1],     wv[q]);
                ffma2(acc[2][q], pp[ky + 1][kx],     wv[q]);
                ffma2(acc[3][q], pp[ky + 1][kx + 1], wv[q]);
            }
        }
    }

    int oplane = h2 * w2;
    float* ob = g_p1 + m.offP[k] + b * 10 * oplane + y * w2 + x;
#pragma unroll
    for (int q = 0; q < 5; q++) {
        float z0, z1, a0, a1, u0, u1;
        unpk(acc[0][q], z0, z1); a0 = lrelu(z0); a1 = lrelu(z1);
        if (vc) { unpk(acc[1][q], z0, z1); a0 = fmaxf(a0, lrelu(z0)); a1 = fmaxf(a1, lrelu(z1)); }
        if (vr) { unpk(acc[2][q], z0, z1); a0 = fmaxf(a0, lrelu(z0)); a1 = fmaxf(a1, lrelu(z1));
            if (vc) { unpk(acc[3][q], u0, u1); a0 = fmaxf(a0, lrelu(u0)); a1 = fmaxf(a1, lrelu(u1)); } }
        ob[(2 * q)     * oplane] = a0;
        ob[(2 * q + 1) * oplane] = a1;
    }
}

// ---------------------------------------------------------------------------
// Stage 4: conv3x3 10->16 + lrelu. TX=4 (R7 shape). Double-buffered input.
// ---------------------------------------------------------------------------
__global__ void __launch_bounds__(128, 4)
k_conv2(const float* __restrict__ w, const float* __restrict__ bias, Meta m)
{
    __shared__ __align__(16) float ws_[1440];
    __shared__ __align__(8)  float bs_[16];
    {
        const float4* s4 = (const float4*)w;
        float4* d4 = (float4*)ws_;
        for (int i = threadIdx.x; i < 360; i += blockDim.x) d4[i] = s4[i];
        if (threadIdx.x < 16) bs_[threadIdx.x] = bias[threadIdx.x];
    }
    __syncthreads();

    int k = fscale(m.bsC2);
    int hs = m.hs[k];
    int hin = (hs - 1) >> 1, win = hin;
    int hout = hin - 2, wout = win - 2;
    int WG = (wout + 3) >> 2;
    int idx = (blockIdx.x - m.bsC2[k]) * blockDim.x + threadIdx.x;
    if (idx >= BATCH * hout * WG) return;
    int xg = idx % WG;
    int t2 = idx / WG;
    int y  = t2 % hout;
    int b  = t2 / hout;
    int x0 = xg * 4;

    u64 acc[4][8];
    {
        const u64* bq = (const u64*)bs_;
#pragma unroll
        for (int q = 0; q < 8; q++) {
            u64 bv = bq[q];
            acc[0][q] = bv; acc[1][q] = bv; acc[2][q] = bv; acc[3][q] = bv;
        }
    }

    int plane = hin * win;
    const float* pb = g_p1 + m.offP[k] + b * 10 * plane;
    int xc[6];
#pragma unroll
    for (int t = 0; t < 6; t++) { int xx = x0 + t; xc[t] = xx > win - 1 ? win - 1 : xx; }

#pragma unroll
    for (int ky = 0; ky < 3; ky++) {
        const float* rbase = pb + (y + ky) * win;
        u64 vbuf[2][6];
#pragma unroll
        for (int t = 0; t < 6; t++) vbuf[0][t] = pack2(__ldg(rbase + xc[t]));

#pragma unroll 2
        for (int ic = 0; ic < 10; ic++) {
            int cur = ic & 1;
            if (ic < 9) {
                const float* rn = rbase + (ic + 1) * plane;
#pragma unroll
                for (int t = 0; t < 6; t++) vbuf[cur ^ 1][t] = pack2(__ldg(rn + xc[t]));
            }
#pragma unroll
            for (int kx = 0; kx < 3; kx++) {
                const ulonglong2* wq = (const ulonglong2*)(ws_ + ((ky * 3 + kx) * 10 + ic) * 16);
#pragma unroll
                for (int q2 = 0; q2 < 4; q2++) {
                    ulonglong2 wv = wq[q2];
#pragma unroll
                    for (int t = 0; t < 4; t++) {
                        ffma2(acc[t][2 * q2 + 0], vbuf[cur][t + kx], wv.x);
                        ffma2(acc[t][2 * q2 + 1], vbuf[cur][t + kx], wv.y);
                    }
                }
            }
        }
    }

    int oplane = hout * wout;
    float* ob = g_c2 + m.offC[k] + b * 16 * oplane + y * wout;
#pragma unroll
    for (int t = 0; t < 4; t++) {
        int x = x0 + t;
        if (x < wout) {
#pragma unroll
            for (int q = 0; q < 8; q++) {
                float z0, z1;
                unpk(acc[t][q], z0, z1);
                ob[(2 * q)     * oplane + x] = lrelu(z0);
                ob[(2 * q + 1) * oplane + x] = lrelu(z1);
            }
        }
    }
}

// ---------------------------------------------------------------------------
// Stage 5: conv3x3 16->32 + lrelu + heads + boxes + mask. TX=2 (R7 shape).
// Output layout: boxes[4][N][5] | reg[4][N][4] | mask[4][N]
// ---------------------------------------------------------------------------
__global__ void __launch_bounds__(128, 4)
k_conv3head(const float* __restrict__ w, const float* __restrict__ bias,
            const float* __restrict__ wp, const float* __restrict__ bp,
            const float* __restrict__ wr, const float* __restrict__ br,
            float* __restrict__ out, Meta m)
{
    __shared__ __align__(16) float ws_[4608];
    __shared__ __align__(8)  float cb_[32], hwp[64], hwr[128], hb[6];
    {
        const float4* s4 = (const float4*)w;
        float4* d4 = (float4*)ws_;
        for (int i = threadIdx.x; i < 1152; i += blockDim.x) d4[i] = s4[i];
        if (threadIdx.x < 32) cb_[threadIdx.x] = bias[threadIdx.x];
        if (threadIdx.x < 64) hwp[threadIdx.x] = wp[threadIdx.x];
        hwr[threadIdx.x] = wr[threadIdx.x];
        if (threadIdx.x == 64) { hb[0] = bp[0]; hb[1] = bp[1]; }
        if (threadIdx.x == 65) { hb[2] = br[0]; hb[3] = br[1]; hb[4] = br[2]; hb[5] = br[3]; }
    }
    __syncthreads();

    int k = fscale(m.bsC3);
    int hs = m.hs[k];
    int hin = ((hs - 1) >> 1) - 2, win = hin;
    int hout = hin - 2, wout = win - 2;
    int WG = (wout + 1) >> 1;
    int idx = (blockIdx.x - m.bsC3[k]) * blockDim.x + threadIdx.x;
    if (idx >= BATCH * hout * WG) return;
    int xg = idx % WG;
    int t2 = idx / WG;
    int y  = t2 % hout;
    int b  = t2 / hout;
    int x0 = xg * 2;

    u64 acc[2][16];
    {
        const u64* bq = (const u64*)cb_;
#pragma unroll
        for (int q = 0; q < 16; q++) {
            u64 bv = bq[q];
            acc[0][q] = bv; acc[1][q] = bv;
        }
    }

    int plane = hin * win;
    const float* cb = g_c2 + m.offC[k] + b * 16 * plane;
    int xc[4];
#pragma unroll
    for (int t = 0; t < 4; t++) { int xx = x0 + t; xc[t] = xx > win - 1 ? win - 1 : xx; }

#pragma unroll
    for (int ky = 0; ky < 3; ky++) {
        const float* rbase = cb + (y + ky) * win;
        u64 vbuf[2][4];
#pragma unroll
        for (int t = 0; t < 4; t++) vbuf[0][t] = pack2(__ldg(rbase + xc[t]));

#pragma unroll 2
        for (int ic = 0; ic < 16; ic++) {
            int cur = ic & 1;
            if (ic < 15) {
                const float* rn = rbase + (ic + 1) * plane;
#pragma unroll
                for (int t = 0; t < 4; t++) vbuf[cur ^ 1][t] = pack2(__ldg(rn + xc[t]));
            }
#pragma unroll
            for (int kx = 0; kx < 3; kx++) {
                const ulonglong2* wq = (const ulonglong2*)(ws_ + ((ky * 3 + kx) * 16 + ic) * 32);
#pragma unroll
                for (int q2 = 0; q2 < 8; q2++) {
                    ulonglong2 wv = wq[q2];
                    ffma2(acc[0][2 * q2 + 0], vbuf[cur][kx],     wv.x);
                    ffma2(acc[0][2 * q2 + 1], vbuf[cur][kx],     wv.y);
                    ffma2(acc[1][2 * q2 + 0], vbuf[cur][kx + 1], wv.x);
                    ffma2(acc[1][2 * q2 + 1], vbuf[cur][kx + 1], wv.y);
                }
            }
        }
    }

    int ntot = m.ntot;
    float scale = m.scl[k];
    int nbase = m.noff[k] + y * wout;
    float fy = (float)y;
    const u64* wp64 = (const u64*)hwp;
    const u64* wr64 = (const u64*)hwr;

#pragma unroll
    for (int t = 0; t < 2; t++) {
        int x = x0 + t;
        if (x >= wout) continue;

        u64 zz = pk2(hb[0], hb[1]);
        u64 rA = pk2(hb[2], hb[3]);
        u64 rB = pk2(hb[4], hb[5]);
#pragma unroll
        for (int q = 0; q < 16; q++) {
            float z0, z1;
            unpk(acc[t][q], z0, z1);
            u64 v0 = pack2(lrelu(z0));
            u64 v1 = pack2(lrelu(z1));
            int c0 = 2 * q, c1 = 2 * q + 1;
            ffma2(zz, v0, wp64[c0]);         ffma2(zz, v1, wp64[c1]);
            ffma2(rA, v0, wr64[2 * c0]);     ffma2(rA, v1, wr64[2 * c1]);
            ffma2(rB, v0, wr64[2 * c0 + 1]); ffma2(rB, v1, wr64[2 * c1 + 1]);
        }
        float z0, z1, r0, r1, r2, r3;
        unpk(zz, z0, z1);
        unpk(rA, r0, r1);
        unpk(rB, r2, r3);
        float score = 1.f / (1.f + expf(z0 - z1));

        int n = nbase + x;
        float fx = (float)x;
        float ulr = rintf((fy * 2.f + 1.f)  / scale);
        float ulc = rintf((fx * 2.f + 1.f)  / scale);
        float drr = rintf((fy * 2.f + 12.f) / scale);
        float drc = rintf((fx * 2.f + 12.f) / scale);

        float* pbx = out + (b * ntot + n) * 5;
        pbx[0] = ulr; pbx[1] = ulc; pbx[2] = drr; pbx[3] = drc; pbx[4] = score;

        float* prg = out + BATCH * ntot * 5 + (b * ntot + n) * 4;
        prg[0] = r0; prg[1] = r1; prg[2] = r2; prg[3] = r3;

        out[BATCH * ntot * 9 + b * ntot + n] = (score >= 0.6f) ? 1.f : 0.f;
    }
}

// ---------------------------------------------------------------------------
extern "C" void kernel_launch(void* const* d_in, const int* in_sizes, int n_in,
                              void* d_out, int out_size)
{
    const float* inp = (const float*)d_in[0];
    const float* w1  = (const float*)d_in[1];
    const float* b1  = (const float*)d_in[2];
    const float* w2  = (const float*)d_in[3];
    const float* b2  = (const float*)d_in[4];
    const float* w3  = (const float*)d_in[5];
    const float* b3  = (const float*)d_in[6];
    const float* wp  = (const float*)d_in[7];
    const float* bp  = (const float*)d_in[8];
    const float* wr  = (const float*)d_in[9];
    const float* br  = (const float*)d_in[10];
    float* out = (float*)d_out;
    (void)in_sizes; (void)n_in; (void)out_size;

    Meta m;
    int ns = 0;
    {
        double s = 12.0 / 20.0, mm = s * 1080.0;
        while (mm >= 12.0 && ns < NS) {
            m.hs[ns]   = (int)ceil(1080.0 * s);
            m.inv[ns]  = (float)(1080.0 / (double)m.hs[ns]);
            m.rinv[ns] = (float)((double)m.hs[ns] / 1080.0);
            m.scl[ns]  = (float)s;
            ns++;
            s *= 0.709; mm *= 0.709;
        }
    }

    int oT = 0, oI = 0, oP = 0, oC = 0, oW = 0, ntot = 0;
    m.bsRV[0] = m.bsCP[0] = m.bsC2[0] = m.bsC3[0] = 0;
    for (int k = 0; k < ns; k++) {
        int hs = m.hs[k], ws = hs;
        int h1 = hs - 2;
        int h2 = (h1 + 1) / 2, w2d = h2;
        int h3 = h2 - 2, w3d = h3;
        int h4 = h3 - 2, w4 = h4;

        m.offT[k] = oT;  oT += BATCH * HIN * ws * 3;
        m.offI[k] = oI;  oI += BATCH * hs * ws * 3;
        m.offP[k] = oP;  oP += BATCH * h2 * w2d * 10;
        m.offC[k] = oC;  oC += BATCH * h3 * w3d * 16;
        m.offW[k] = oW;  oW += ws;
        m.noff[k] = ntot; ntot += h4 * w4;

        int T;
        T = BATCH * hs * ws;                  m.bsRV[k+1] = m.bsRV[k] + (T + 255) / 256;
        T = BATCH * h2 * w2d;                 m.bsCP[k+1] = m.bsCP[k] + (T + 127) / 128;
        T = BATCH * h3 * ((w2d - 2 + 3) / 4); m.bsC2[k+1] = m.bsC2[k] + (T + 127) / 128;
        T = BATCH * h4 * ((w4 + 1) / 2);      m.bsC3[k+1] = m.bsC3[k] + (T + 127) / 128;
    }
    m.ntot = ntot;
    m.wsum = oW;
    for (int k = ns; k < NS; k++) {
        m.hs[k] = m.hs[ns-1]; m.inv[k] = m.inv[ns-1];
        m.rinv[k] = m.rinv[ns-1]; m.scl[k] = m.scl[ns-1];
        m.offT[k] = m.offI[k] = m.offP[k] = m.offC[k] = 0; m.noff[k] = 0;
        m.bsRV[k+1] = m.bsRV[k];
        m.bsCP[k+1] = m.bsCP[k]; m.bsC2[k+1] = m.bsC2[k]; m.bsC3[k+1] = m.bsC3[k];
        m.offW[k] = 0x7fffffff;
        m.bsRV[k] = 0x7fffffff; m.bsCP[k] = 0x7fffffff;
        m.bsC2[k] = 0x7fffffff; m.bsC3[k] = 0x7fffffff;
    }

    k_resize_h <<<BATCH * HIN, 256>>>(inp, m);
    k_resize_v <<<m.bsRV[ns], 256>>>(m);
    k_conv1pool<<<m.bsCP[ns], 128>>>(w1, b1, m);
    k_conv2    <<<m.bsC2[ns], 128>>>(w2, b2, m);
    k_conv3head<<<m.bsC3[ns], 128>>>(w3, b3, wp, bp, wr, br, out, m);
}